// round 16
// baseline (speedup 1.0000x reference)
#include <cuda_runtime.h>
#include <cuda_fp16.h>

#define N_NODES 50000
#define N_EDGES 600000
#define N_GRAPHS 64
#define HID 128
#define EMB 64
#define BN_EPS 1e-5f
#define NB_CSR 196             // ceil(50000/256)
#define XS_STRIDE 8
#define AST 136                // smem row stride in halfs

// ------------------------- scratch (device globals; no allocs) -------------
__device__ float  g_dinv[N_NODES];
__device__ float  g_xs [N_NODES * XS_STRIDE];
__device__ __half g_hw [N_NODES * HID];       // fp16: (h @ W) * dinv
__device__ __half g_h  [N_NODES * HID];       // fp16 activations
__device__ __half g_Wt2[HID * HID];           // W2^T fp16 [n][k]
__device__ __half g_Wt3[HID * HID];           // W3^T fp16 [n][k]
__device__ float  g_sums[N_GRAPHS * HID];
__device__ int    g_cnti[N_GRAPHS];
__device__ int    g_rowcnt[N_NODES];
__device__ int    g_rowptr[N_NODES];
__device__ int    g_cursor[N_NODES];
__device__ int    g_col[N_EDGES];
__device__ int    g_total;

__device__ __forceinline__ void red2(float* p, float2 v) {
    asm volatile("red.global.add.v2.f32 [%0], {%1,%2};"
                 :: "l"(p), "f"(v.x), "f"(v.y)
                 : "memory");
}

// ------------------------- CSR build + weight prep --------------------------
__global__ void zero_wt_kernel(const float* __restrict__ W2, const float* __restrict__ W3) {
    int i = blockIdx.x * blockDim.x + threadIdx.x;
    if (i < N_NODES) g_rowcnt[i] = 0;
    if (i < N_GRAPHS * HID) g_sums[i] = 0.0f;
    if (i < N_GRAPHS) g_cnti[i] = 0;
    if (i == 0) g_total = 0;
    if (i < HID * HID) {
        int k = i >> 7, n = i & 127;
        g_Wt2[n * HID + k] = __float2half_rn(W2[i]);
        g_Wt3[n * HID + k] = __float2half_rn(W3[i]);
    }
}

__global__ void hist_kernel(const int* __restrict__ dst, const int* __restrict__ batch) {
    int t = blockIdx.x * blockDim.x + threadIdx.x;
    if (t < N_EDGES) atomicAdd(&g_rowcnt[dst[t]], 1);
    if (t < N_NODES) {
        int g = batch[t];
        unsigned act = __activemask();
        unsigned m = __match_any_sync(act, g);
        int leader = __ffs(m) - 1;
        if ((int)(threadIdx.x & 31) == leader) atomicAdd(&g_cnti[g], __popc(m));
    }
}

__global__ void offset_kernel(const float* __restrict__ x) {
    int i = blockIdx.x * 256 + threadIdx.x;
    int lane = threadIdx.x & 31;
    int c = (i < N_NODES) ? g_rowcnt[i] : 0;
    if (i < N_NODES) {
        float di = rsqrtf((float)(c + 1));
        g_dinv[i] = di;
        #pragma unroll
        for (int k = 0; k < 5; k++) g_xs[i * XS_STRIDE + k] = __ldg(x + i * 5 + k) * di;
    }
    int incl = c;
    #pragma unroll
    for (int off = 1; off < 32; off <<= 1) {
        int v = __shfl_up_sync(0xffffffffu, incl, off);
        if (lane >= off) incl += v;
    }
    int tot = __shfl_sync(0xffffffffu, incl, 31);
    int base = 0;
    if (lane == 31) base = atomicAdd(&g_total, tot);
    base = __shfl_sync(0xffffffffu, base, 31);
    if (i < N_NODES) {
        int start = base + incl - c;
        g_rowptr[i] = start;
        g_cursor[i] = start;
    }
}

__global__ void fill_kernel(const int* __restrict__ src, const int* __restrict__ dst) {
    int e = blockIdx.x * blockDim.x + threadIdx.x;
    if (e < N_EDGES) {
        int p = atomicAdd(&g_cursor[dst[e]], 1);
        g_col[p] = src[e];
    }
}

// ------------------------- fused layer 1 ------------------------------------
__global__ void __launch_bounds__(256)
layer1_kernel(const float* __restrict__ W1, const float* __restrict__ b1,
              const float* __restrict__ gm, const float* __restrict__ be) {
    int n = blockIdx.x * 8 + (threadIdx.x >> 5);
    if (n >= N_NODES) return;
    int lane = threadIdx.x & 31;

    float a0 = 0.f, a1 = 0.f, a2 = 0.f, a3 = 0.f, a4 = 0.f;
    int start = g_rowptr[n];
    int end   = start + g_rowcnt[n];
    for (int j = start + lane; j < end; j += 32) {
        int s = g_col[j];
        float4 v = *(const float4*)(g_xs + s * XS_STRIDE);
        float  w = g_xs[s * XS_STRIDE + 4];
        a0 += v.x; a1 += v.y; a2 += v.z; a3 += v.w; a4 += w;
    }
    #pragma unroll
    for (int off = 16; off > 0; off >>= 1) {
        a0 += __shfl_xor_sync(0xffffffffu, a0, off);
        a1 += __shfl_xor_sync(0xffffffffu, a1, off);
        a2 += __shfl_xor_sync(0xffffffffu, a2, off);
        a3 += __shfl_xor_sync(0xffffffffu, a3, off);
        a4 += __shfl_xor_sync(0xffffffffu, a4, off);
    }
    float4 sv = *(const float4*)(g_xs + n * XS_STRIDE);
    a0 += sv.x; a1 += sv.y; a2 += sv.z; a3 += sv.w; a4 += g_xs[n * XS_STRIDE + 4];

    float di = g_dinv[n];
    float rs = rsqrtf(1.0f + BN_EPS);
    float4 w0 = __ldg((const float4*)(W1 + 0 * HID) + lane);
    float4 w1 = __ldg((const float4*)(W1 + 1 * HID) + lane);
    float4 w2 = __ldg((const float4*)(W1 + 2 * HID) + lane);
    float4 w3 = __ldg((const float4*)(W1 + 3 * HID) + lane);
    float4 w4 = __ldg((const float4*)(W1 + 4 * HID) + lane);
    float4 bb = __ldg((const float4*)b1 + lane);
    float4 gg = __ldg((const float4*)gm + lane);
    float4 ee = __ldg((const float4*)be + lane);

    float4 v;
    v.x = fmaxf(((a0*w0.x + a1*w1.x + a2*w2.x + a3*w3.x + a4*w4.x) * di + bb.x) * (gg.x*rs) + ee.x, 0.f);
    v.y = fmaxf(((a0*w0.y + a1*w1.y + a2*w2.y + a3*w3.y + a4*w4.y) * di + bb.y) * (gg.y*rs) + ee.y, 0.f);
    v.z = fmaxf(((a0*w0.z + a1*w1.z + a2*w2.z + a3*w3.z + a4*w4.z) * di + bb.z) * (gg.z*rs) + ee.z, 0.f);
    v.w = fmaxf(((a0*w0.w + a1*w1.w + a2*w2.w + a3*w3.w + a4*w4.w) * di + bb.w) * (gg.w*rs) + ee.w, 0.f);

    __half2 h01 = __floats2half2_rn(v.x, v.y);
    __half2 h23 = __floats2half2_rn(v.z, v.w);
    uint2 u = make_uint2(*(unsigned*)&h01, *(unsigned*)&h23);
    *(uint2*)(g_h + n * HID + lane * 4) = u;
}

// ------------------------- HMMA 128x128 GEMM (layers 2/3) -------------------
__global__ void __launch_bounds__(512, 2)
gemm128_kernel(const __half* __restrict__ Wt) {
    extern __shared__ __half smem_h[];
    __half* As = smem_h;               // 128 x AST
    __half* Bs = smem_h + 128 * AST;   // 128(n) x AST(k)

    int i0 = blockIdx.x * 128;
    int t  = threadIdx.x;

    #pragma unroll
    for (int it = 0; it < 4; it++) {
        int idx = it * 512 + t;            // 0..2047 uint4s
        int row = idx >> 4, seg = idx & 15;
        int gi  = i0 + row;
        uint4 v = make_uint4(0u, 0u, 0u, 0u);
        if (gi < N_NODES) v = *(const uint4*)(g_h + gi * HID + seg * 8);
        *(uint4*)(As + row * AST + seg * 8) = v;

        *(uint4*)(Bs + row * AST + seg * 8) = *(const uint4*)(Wt + row * HID + seg * 8);
    }
    __syncthreads();

    int w = t >> 5, lane = t & 31;
    int r0 = (w & 7) * 16;
    int nb = (w >> 3) * 64;
    int g = lane >> 2, tq = lane & 3;

    float acc[8][4];
    #pragma unroll
    for (int nt = 0; nt < 8; nt++)
        #pragma unroll
        for (int j = 0; j < 4; j++) acc[nt][j] = 0.f;

    const __half* Ar0 = As + (r0 + g) * AST;
    const __half* Ar1 = As + (r0 + g + 8) * AST;

    #pragma unroll
    for (int ks = 0; ks < 8; ks++) {
        int k0 = ks * 16;
        unsigned a0 = *(const unsigned*)(Ar0 + k0 + 2 * tq);
        unsigned a1 = *(const unsigned*)(Ar1 + k0 + 2 * tq);
        unsigned a2 = *(const unsigned*)(Ar0 + k0 + 8 + 2 * tq);
        unsigned a3 = *(const unsigned*)(Ar1 + k0 + 8 + 2 * tq);
        #pragma unroll
        for (int nt = 0; nt < 8; nt++) {
            const __half* Bn = Bs + (nb + nt * 8 + g) * AST;
            unsigned b0 = *(const unsigned*)(Bn + k0 + 2 * tq);
            unsigned b1 = *(const unsigned*)(Bn + k0 + 8 + 2 * tq);
            asm volatile(
                "mma.sync.aligned.m16n8k16.row.col.f32.f16.f16.f32 "
                "{%0,%1,%2,%3}, {%4,%5,%6,%7}, {%8,%9}, {%0,%1,%2,%3};"
                : "+f"(acc[nt][0]), "+f"(acc[nt][1]), "+f"(acc[nt][2]), "+f"(acc[nt][3])
                : "r"(a0), "r"(a1), "r"(a2), "r"(a3), "r"(b0), "r"(b1));
        }
    }

    int gr1 = i0 + r0 + g;
    int gr2 = gr1 + 8;
    float s1 = (gr1 < N_NODES) ? g_dinv[gr1] : 0.f;
    float s2 = (gr2 < N_NODES) ? g_dinv[gr2] : 0.f;
    #pragma unroll
    for (int nt = 0; nt < 8; nt++) {
        int c0 = nb + nt * 8 + 2 * tq;
        if (gr1 < N_NODES) {
            __half2 o = __floats2half2_rn(acc[nt][0] * s1, acc[nt][1] * s1);
            *(unsigned*)(g_hw + gr1 * HID + c0) = *(unsigned*)&o;
        }
        if (gr2 < N_NODES) {
            __half2 o = __floats2half2_rn(acc[nt][2] * s2, acc[nt][3] * s2);
            *(unsigned*)(g_hw + gr2 * HID + c0) = *(unsigned*)&o;
        }
    }
}

// ------------------------- fused gather-aggregate + bn + relu ---------------
// Split-feature: warp w handles node w>>1, feature-half w&1 (64 features).
// Gathers are LDG.32 (one half2 per lane). fp32 accumulation, unroll-2.
template<bool POOL>
__global__ void __launch_bounds__(128)
agg_kernel(const float* __restrict__ b, const float* __restrict__ gm,
           const float* __restrict__ be, const int* __restrict__ batch) {
    int w = blockIdx.x * 4 + (threadIdx.x >> 5);
    int n = w >> 1;
    if (n >= N_NODES) return;
    int h = w & 1;
    int lane = threadIdx.x & 31;
    const unsigned* hw = (const unsigned*)g_hw;    // half2 units
    int off = h * 32 + lane;                        // half2 index within row

    unsigned us = __ldg(hw + n * 64 + off);
    float2 accA = __half22float2(*(__half2*)&us);
    float2 accB = make_float2(0.f, 0.f);

    int start = g_rowptr[n];
    int end   = start + g_rowcnt[n];
    for (int base = start; base < end; base += 32) {
        int j = base + lane;
        int idx = (j < end) ? g_col[j] : 0;
        int m = end - base; if (m > 32) m = 32;
        int k = 0;
        for (; k + 1 < m; k += 2) {
            int sA = __shfl_sync(0xffffffffu, idx, k);
            int sB = __shfl_sync(0xffffffffu, idx, k + 1);
            unsigned uA = __ldg(hw + sA * 64 + off);
            unsigned uB = __ldg(hw + sB * 64 + off);
            float2 a = __half22float2(*(__half2*)&uA);
            float2 c = __half22float2(*(__half2*)&uB);
            accA.x += a.x; accA.y += a.y;
            accB.x += c.x; accB.y += c.y;
        }
        if (k < m) {
            int sA = __shfl_sync(0xffffffffu, idx, k);
            unsigned uA = __ldg(hw + sA * 64 + off);
            float2 a = __half22float2(*(__half2*)&uA);
            accA.x += a.x; accA.y += a.y;
        }
    }
    accA.x += accB.x; accA.y += accB.y;

    float di = g_dinv[n];
    float rs = rsqrtf(1.0f + BN_EPS);
    float2 bb = __ldg((const float2*)b  + off);
    float2 gg = __ldg((const float2*)gm + off);
    float2 ee = __ldg((const float2*)be + off);
    float2 v;
    v.x = fmaxf((accA.x * di + bb.x) * (gg.x * rs) + ee.x, 0.f);
    v.y = fmaxf((accA.y * di + bb.y) * (gg.y * rs) + ee.y, 0.f);

    if (POOL) {
        int g = __ldg(batch + n);
        red2(g_sums + g * HID + off * 2, v);
    } else {
        __half2 hv = __floats2half2_rn(v.x, v.y);
        *(unsigned*)(g_h + n * HID + off * 2) = *(unsigned*)&hv;
    }
}

// ------------------------- final projection ---------------------------------
__global__ void final_kernel(const float* __restrict__ Wp, const float* __restrict__ bp,
                             float* __restrict__ out) {
    __shared__ float p[HID];
    int g = blockIdx.x, j = threadIdx.x;
    float invc = 1.0f / fmaxf((float)g_cnti[g], 1.0f);
    for (int c = j; c < HID; c += EMB) p[c] = g_sums[g * HID + c] * invc;
    __syncthreads();
    float acc = __ldg(bp + j);
    #pragma unroll 8
    for (int c = 0; c < HID; c++) acc += p[c] * __ldg(Wp + c * EMB + j);
    out[g * EMB + j] = acc;
}

// ------------------------- launch -------------------------------------------
extern "C" void kernel_launch(void* const* d_in, const int* in_sizes, int n_in,
                              void* d_out, int out_size) {
    const float* x   = (const float*)d_in[0];
    const int*   src = (const int*)  d_in[1];
    const int*   dst = (const int*)  d_in[2];
    const int*   bat = (const int*)  d_in[3];
    const float* W1  = (const float*)d_in[4];
    const float* b1  = (const float*)d_in[5];
    const float* W2  = (const float*)d_in[6];
    const float* b2  = (const float*)d_in[7];
    const float* W3  = (const float*)d_in[8];
    const float* b3  = (const float*)d_in[9];
    const float* g1  = (const float*)d_in[10];
    const float* be1 = (const float*)d_in[11];
    const float* g2  = (const float*)d_in[12];
    const float* be2 = (const float*)d_in[13];
    const float* g3  = (const float*)d_in[14];
    const float* be3 = (const float*)d_in[15];
    const float* Wp  = (const float*)d_in[16];
    const float* bp  = (const float*)d_in[17];
    float* out = (float*)d_out;

    const __half* wt2;
    const __half* wt3;
    cudaGetSymbolAddress((void**)&wt2, g_Wt2);
    cudaGetSymbolAddress((void**)&wt3, g_Wt3);

    const int SMEM = 2 * 128 * AST * (int)sizeof(__half);   // ~68 KB
    cudaFuncSetAttribute(gemm128_kernel, cudaFuncAttributeMaxDynamicSharedMemorySize, SMEM);

    const int GEMM_BLOCKS = (N_NODES + 127) / 128;
    const int AGG_BLOCKS  = (2 * N_NODES + 3) / 4;   // 2 warps per node, 4 warps/block

    // CSR build + weight prep
    zero_wt_kernel<<<(N_NODES + 255) / 256, 256>>>(W2, W3);
    hist_kernel   <<<(N_EDGES + 255) / 256, 256>>>(dst, bat);
    offset_kernel <<<NB_CSR, 256>>>(x);
    fill_kernel   <<<(N_EDGES + 255) / 256, 256>>>(src, dst);

    // layer 1
    layer1_kernel<<<(N_NODES + 7) / 8, 256>>>(W1, b1, g1, be1);

    // layer 2
    gemm128_kernel<<<GEMM_BLOCKS, 512, SMEM>>>(wt2);
    agg_kernel<false><<<AGG_BLOCKS, 128>>>(b2, g2, be2, bat);

    // layer 3 (+ fused mean-pool accumulation)
    gemm128_kernel<<<GEMM_BLOCKS, 512, SMEM>>>(wt3);
    agg_kernel<true><<<AGG_BLOCKS, 128>>>(b3, g3, be3, bat);

    final_kernel<<<N_GRAPHS, EMB>>>(Wp, bp, out);
}

// round 17
// speedup vs baseline: 1.2696x; 1.2696x over previous
#include <cuda_runtime.h>
#include <cuda_fp16.h>

#define N_NODES 50000
#define N_EDGES 600000
#define N_GRAPHS 64
#define HID 128
#define EMB 64
#define BN_EPS 1e-5f
#define NB_CSR 196             // ceil(50000/256)
#define XS_STRIDE 8
#define AST 136                // smem row stride in halfs

// ------------------------- scratch (device globals; no allocs) -------------
__device__ float  g_dinv[N_NODES];
__device__ float  g_xs [N_NODES * XS_STRIDE];
__device__ __half g_hw [N_NODES * HID];       // fp16: (h @ W) * dinv
__device__ __half g_h  [N_NODES * HID];       // fp16 activations
__device__ __half g_Wt2[HID * HID];           // W2^T fp16 [n][k]
__device__ __half g_Wt3[HID * HID];           // W3^T fp16 [n][k]
__device__ float  g_sums[N_GRAPHS * HID];
__device__ int    g_cnti[N_GRAPHS];
__device__ int    g_rowcnt[N_NODES];
__device__ int    g_rowptr[N_NODES];
__device__ int    g_cursor[N_NODES];
__device__ int    g_col[N_EDGES];
__device__ int    g_total;

__device__ __forceinline__ void red4(float* p, float4 v) {
    asm volatile("red.global.add.v4.f32 [%0], {%1,%2,%3,%4};"
                 :: "l"(p), "f"(v.x), "f"(v.y), "f"(v.z), "f"(v.w)
                 : "memory");
}

// ------------------------- CSR build + weight prep --------------------------
__global__ void zero_wt_kernel(const float* __restrict__ W2, const float* __restrict__ W3) {
    int i = blockIdx.x * blockDim.x + threadIdx.x;
    if (i < N_NODES) g_rowcnt[i] = 0;
    if (i < N_GRAPHS * HID) g_sums[i] = 0.0f;
    if (i < N_GRAPHS) g_cnti[i] = 0;
    if (i == 0) g_total = 0;
    if (i < HID * HID) {
        int k = i >> 7, n = i & 127;
        g_Wt2[n * HID + k] = __float2half_rn(W2[i]);
        g_Wt3[n * HID + k] = __float2half_rn(W3[i]);
    }
}

__global__ void hist_kernel(const int* __restrict__ dst, const int* __restrict__ batch) {
    int t = blockIdx.x * blockDim.x + threadIdx.x;
    if (t < N_EDGES) atomicAdd(&g_rowcnt[dst[t]], 1);
    if (t < N_NODES) {
        int g = batch[t];
        unsigned act = __activemask();
        unsigned m = __match_any_sync(act, g);
        int leader = __ffs(m) - 1;
        if ((int)(threadIdx.x & 31) == leader) atomicAdd(&g_cnti[g], __popc(m));
    }
}

__global__ void offset_kernel(const float* __restrict__ x) {
    int i = blockIdx.x * 256 + threadIdx.x;
    int lane = threadIdx.x & 31;
    int c = (i < N_NODES) ? g_rowcnt[i] : 0;
    if (i < N_NODES) {
        float di = rsqrtf((float)(c + 1));
        g_dinv[i] = di;
        #pragma unroll
        for (int k = 0; k < 5; k++) g_xs[i * XS_STRIDE + k] = __ldg(x + i * 5 + k) * di;
    }
    int incl = c;
    #pragma unroll
    for (int off = 1; off < 32; off <<= 1) {
        int v = __shfl_up_sync(0xffffffffu, incl, off);
        if (lane >= off) incl += v;
    }
    int tot = __shfl_sync(0xffffffffu, incl, 31);
    int base = 0;
    if (lane == 31) base = atomicAdd(&g_total, tot);
    base = __shfl_sync(0xffffffffu, base, 31);
    if (i < N_NODES) {
        int start = base + incl - c;
        g_rowptr[i] = start;
        g_cursor[i] = start;
    }
}

__global__ void fill_kernel(const int* __restrict__ src, const int* __restrict__ dst) {
    int e = blockIdx.x * blockDim.x + threadIdx.x;
    if (e < N_EDGES) {
        int p = atomicAdd(&g_cursor[dst[e]], 1);
        g_col[p] = src[e];
    }
}

// ------------------------- fused layer 1 ------------------------------------
__global__ void __launch_bounds__(128)
layer1_kernel(const float* __restrict__ W1, const float* __restrict__ b1,
              const float* __restrict__ gm, const float* __restrict__ be) {
    int n = blockIdx.x * 4 + (threadIdx.x >> 5);
    if (n >= N_NODES) return;
    int lane = threadIdx.x & 31;

    float a0 = 0.f, a1 = 0.f, a2 = 0.f, a3 = 0.f, a4 = 0.f;
    int start = g_rowptr[n];
    int end   = start + g_rowcnt[n];
    for (int j = start + lane; j < end; j += 32) {
        int s = __ldg(g_col + j);
        float4 v = __ldg((const float4*)(g_xs + s * XS_STRIDE));
        float  w = __ldg(g_xs + s * XS_STRIDE + 4);
        a0 += v.x; a1 += v.y; a2 += v.z; a3 += v.w; a4 += w;
    }
    #pragma unroll
    for (int off = 16; off > 0; off >>= 1) {
        a0 += __shfl_xor_sync(0xffffffffu, a0, off);
        a1 += __shfl_xor_sync(0xffffffffu, a1, off);
        a2 += __shfl_xor_sync(0xffffffffu, a2, off);
        a3 += __shfl_xor_sync(0xffffffffu, a3, off);
        a4 += __shfl_xor_sync(0xffffffffu, a4, off);
    }
    float4 sv = *(const float4*)(g_xs + n * XS_STRIDE);
    a0 += sv.x; a1 += sv.y; a2 += sv.z; a3 += sv.w; a4 += g_xs[n * XS_STRIDE + 4];

    float di = g_dinv[n];
    float rs = rsqrtf(1.0f + BN_EPS);
    float4 w0 = __ldg((const float4*)(W1 + 0 * HID) + lane);
    float4 w1 = __ldg((const float4*)(W1 + 1 * HID) + lane);
    float4 w2 = __ldg((const float4*)(W1 + 2 * HID) + lane);
    float4 w3 = __ldg((const float4*)(W1 + 3 * HID) + lane);
    float4 w4 = __ldg((const float4*)(W1 + 4 * HID) + lane);
    float4 bb = __ldg((const float4*)b1 + lane);
    float4 gg = __ldg((const float4*)gm + lane);
    float4 ee = __ldg((const float4*)be + lane);

    float4 v;
    v.x = fmaxf(((a0*w0.x + a1*w1.x + a2*w2.x + a3*w3.x + a4*w4.x) * di + bb.x) * (gg.x*rs) + ee.x, 0.f);
    v.y = fmaxf(((a0*w0.y + a1*w1.y + a2*w2.y + a3*w3.y + a4*w4.y) * di + bb.y) * (gg.y*rs) + ee.y, 0.f);
    v.z = fmaxf(((a0*w0.z + a1*w1.z + a2*w2.z + a3*w3.z + a4*w4.z) * di + bb.z) * (gg.z*rs) + ee.z, 0.f);
    v.w = fmaxf(((a0*w0.w + a1*w1.w + a2*w2.w + a3*w3.w + a4*w4.w) * di + bb.w) * (gg.w*rs) + ee.w, 0.f);

    __half2 h01 = __floats2half2_rn(v.x, v.y);
    __half2 h23 = __floats2half2_rn(v.z, v.w);
    uint2 u = make_uint2(*(unsigned*)&h01, *(unsigned*)&h23);
    *(uint2*)(g_h + n * HID + lane * 4) = u;
}

// ------------------------- HMMA 128x128 GEMM (layers 2/3) -------------------
__global__ void __launch_bounds__(512, 2)
gemm128_kernel(const __half* __restrict__ Wt) {
    extern __shared__ __half smem_h[];
    __half* As = smem_h;               // 128 x AST
    __half* Bs = smem_h + 128 * AST;   // 128(n) x AST(k)

    int i0 = blockIdx.x * 128;
    int t  = threadIdx.x;

    #pragma unroll
    for (int it = 0; it < 4; it++) {
        int idx = it * 512 + t;            // 0..2047 uint4s
        int row = idx >> 4, seg = idx & 15;
        int gi  = i0 + row;
        uint4 v = make_uint4(0u, 0u, 0u, 0u);
        if (gi < N_NODES) v = *(const uint4*)(g_h + gi * HID + seg * 8);
        *(uint4*)(As + row * AST + seg * 8) = v;

        *(uint4*)(Bs + row * AST + seg * 8) = *(const uint4*)(Wt + row * HID + seg * 8);
    }
    __syncthreads();

    int w = t >> 5, lane = t & 31;
    int r0 = (w & 7) * 16;
    int nb = (w >> 3) * 64;
    int g = lane >> 2, tq = lane & 3;

    float acc[8][4];
    #pragma unroll
    for (int nt = 0; nt < 8; nt++)
        #pragma unroll
        for (int j = 0; j < 4; j++) acc[nt][j] = 0.f;

    const __half* Ar0 = As + (r0 + g) * AST;
    const __half* Ar1 = As + (r0 + g + 8) * AST;

    #pragma unroll
    for (int ks = 0; ks < 8; ks++) {
        int k0 = ks * 16;
        unsigned a0 = *(const unsigned*)(Ar0 + k0 + 2 * tq);
        unsigned a1 = *(const unsigned*)(Ar1 + k0 + 2 * tq);
        unsigned a2 = *(const unsigned*)(Ar0 + k0 + 8 + 2 * tq);
        unsigned a3 = *(const unsigned*)(Ar1 + k0 + 8 + 2 * tq);
        #pragma unroll
        for (int nt = 0; nt < 8; nt++) {
            const __half* Bn = Bs + (nb + nt * 8 + g) * AST;
            unsigned b0 = *(const unsigned*)(Bn + k0 + 2 * tq);
            unsigned b1 = *(const unsigned*)(Bn + k0 + 8 + 2 * tq);
            asm volatile(
                "mma.sync.aligned.m16n8k16.row.col.f32.f16.f16.f32 "
                "{%0,%1,%2,%3}, {%4,%5,%6,%7}, {%8,%9}, {%0,%1,%2,%3};"
                : "+f"(acc[nt][0]), "+f"(acc[nt][1]), "+f"(acc[nt][2]), "+f"(acc[nt][3])
                : "r"(a0), "r"(a1), "r"(a2), "r"(a3), "r"(b0), "r"(b1));
        }
    }

    int gr1 = i0 + r0 + g;
    int gr2 = gr1 + 8;
    float s1 = (gr1 < N_NODES) ? g_dinv[gr1] : 0.f;
    float s2 = (gr2 < N_NODES) ? g_dinv[gr2] : 0.f;
    #pragma unroll
    for (int nt = 0; nt < 8; nt++) {
        int c0 = nb + nt * 8 + 2 * tq;
        if (gr1 < N_NODES) {
            __half2 o = __floats2half2_rn(acc[nt][0] * s1, acc[nt][1] * s1);
            *(unsigned*)(g_hw + gr1 * HID + c0) = *(unsigned*)&o;
        }
        if (gr2 < N_NODES) {
            __half2 o = __floats2half2_rn(acc[nt][2] * s2, acc[nt][3] * s2);
            *(unsigned*)(g_hw + gr2 * HID + c0) = *(unsigned*)&o;
        }
    }
}

// ------------------------- fused gather-aggregate + bn + relu ---------------
// R15 structure + index-batch prefetch; __ldg gathers; 128-thread blocks.
template<bool POOL>
__global__ void __launch_bounds__(128)
agg_kernel(const float* __restrict__ b, const float* __restrict__ gm,
           const float* __restrict__ be, const int* __restrict__ batch) {
    int n = blockIdx.x * 4 + (threadIdx.x >> 5);
    if (n >= N_NODES) return;
    int lane = threadIdx.x & 31;
    const uint2* hw = (const uint2*)g_hw;   // 8B = 4 halfs per lane

    uint2 us = __ldg(hw + n * 32 + lane);
    float2 s01 = __half22float2(*(__half2*)&us.x);
    float2 s23 = __half22float2(*(__half2*)&us.y);
    float4 accA = make_float4(s01.x, s01.y, s23.x, s23.y);
    float4 accB = make_float4(0.f, 0.f, 0.f, 0.f);

    int start = g_rowptr[n];
    int end   = start + g_rowcnt[n];

    // prefetch first index batch
    int j0 = start + lane;
    int idx = (j0 < end) ? __ldg(g_col + j0) : 0;

    for (int base = start; base < end; base += 32) {
        // prefetch next batch before draining this one
        int jn = base + 32 + lane;
        int nidx = (jn < end) ? __ldg(g_col + jn) : 0;

        int m = end - base; if (m > 32) m = 32;
        int k = 0;
        for (; k + 1 < m; k += 2) {
            int sA = __shfl_sync(0xffffffffu, idx, k);
            int sB = __shfl_sync(0xffffffffu, idx, k + 1);
            uint2 uA = __ldg(hw + sA * 32 + lane);
            uint2 uB = __ldg(hw + sB * 32 + lane);
            float2 a01 = __half22float2(*(__half2*)&uA.x);
            float2 a23 = __half22float2(*(__half2*)&uA.y);
            float2 b01 = __half22float2(*(__half2*)&uB.x);
            float2 b23 = __half22float2(*(__half2*)&uB.y);
            accA.x += a01.x; accA.y += a01.y; accA.z += a23.x; accA.w += a23.y;
            accB.x += b01.x; accB.y += b01.y; accB.z += b23.x; accB.w += b23.y;
        }
        if (k < m) {
            int sA = __shfl_sync(0xffffffffu, idx, k);
            uint2 uA = __ldg(hw + sA * 32 + lane);
            float2 a01 = __half22float2(*(__half2*)&uA.x);
            float2 a23 = __half22float2(*(__half2*)&uA.y);
            accA.x += a01.x; accA.y += a01.y; accA.z += a23.x; accA.w += a23.y;
        }
        idx = nidx;
    }
    accA.x += accB.x; accA.y += accB.y; accA.z += accB.z; accA.w += accB.w;

    float di = g_dinv[n];
    float rs = rsqrtf(1.0f + BN_EPS);
    float4 bb = __ldg((const float4*)b  + lane);
    float4 gg = __ldg((const float4*)gm + lane);
    float4 ee = __ldg((const float4*)be + lane);
    float4 v;
    v.x = fmaxf((accA.x * di + bb.x) * (gg.x * rs) + ee.x, 0.f);
    v.y = fmaxf((accA.y * di + bb.y) * (gg.y * rs) + ee.y, 0.f);
    v.z = fmaxf((accA.z * di + bb.z) * (gg.z * rs) + ee.z, 0.f);
    v.w = fmaxf((accA.w * di + bb.w) * (gg.w * rs) + ee.w, 0.f);

    if (POOL) {
        int g = __ldg(batch + n);
        red4(g_sums + g * HID + lane * 4, v);
    } else {
        __half2 h01 = __floats2half2_rn(v.x, v.y);
        __half2 h23 = __floats2half2_rn(v.z, v.w);
        uint2 u = make_uint2(*(unsigned*)&h01, *(unsigned*)&h23);
        *(uint2*)(g_h + n * HID + lane * 4) = u;
    }
}

// ------------------------- final projection ---------------------------------
__global__ void final_kernel(const float* __restrict__ Wp, const float* __restrict__ bp,
                             float* __restrict__ out) {
    __shared__ float p[HID];
    int g = blockIdx.x, j = threadIdx.x;
    float invc = 1.0f / fmaxf((float)g_cnti[g], 1.0f);
    for (int c = j; c < HID; c += EMB) p[c] = g_sums[g * HID + c] * invc;
    __syncthreads();
    float acc = __ldg(bp + j);
    #pragma unroll 8
    for (int c = 0; c < HID; c++) acc += p[c] * __ldg(Wp + c * EMB + j);
    out[g * EMB + j] = acc;
}

// ------------------------- launch -------------------------------------------
extern "C" void kernel_launch(void* const* d_in, const int* in_sizes, int n_in,
                              void* d_out, int out_size) {
    const float* x   = (const float*)d_in[0];
    const int*   src = (const int*)  d_in[1];
    const int*   dst = (const int*)  d_in[2];
    const int*   bat = (const int*)  d_in[3];
    const float* W1  = (const float*)d_in[4];
    const float* b1  = (const float*)d_in[5];
    const float* W2  = (const float*)d_in[6];
    const float* b2  = (const float*)d_in[7];
    const float* W3  = (const float*)d_in[8];
    const float* b3  = (const float*)d_in[9];
    const float* g1  = (const float*)d_in[10];
    const float* be1 = (const float*)d_in[11];
    const float* g2  = (const float*)d_in[12];
    const float* be2 = (const float*)d_in[13];
    const float* g3  = (const float*)d_in[14];
    const float* be3 = (const float*)d_in[15];
    const float* Wp  = (const float*)d_in[16];
    const float* bp  = (const float*)d_in[17];
    float* out = (float*)d_out;

    const __half* wt2;
    const __half* wt3;
    cudaGetSymbolAddress((void**)&wt2, g_Wt2);
    cudaGetSymbolAddress((void**)&wt3, g_Wt3);

    const int SMEM = 2 * 128 * AST * (int)sizeof(__half);   // ~68 KB
    cudaFuncSetAttribute(gemm128_kernel, cudaFuncAttributeMaxDynamicSharedMemorySize, SMEM);

    const int GEMM_BLOCKS = (N_NODES + 127) / 128;
    const int AGG_BLOCKS  = (N_NODES + 3) / 4;

    // CSR build + weight prep
    zero_wt_kernel<<<(N_NODES + 255) / 256, 256>>>(W2, W3);
    hist_kernel   <<<(N_EDGES + 255) / 256, 256>>>(dst, bat);
    offset_kernel <<<NB_CSR, 256>>>(x);
    fill_kernel   <<<(N_EDGES + 255) / 256, 256>>>(src, dst);

    // layer 1
    layer1_kernel<<<AGG_BLOCKS, 128>>>(W1, b1, g1, be1);

    // layer 2
    gemm128_kernel<<<GEMM_BLOCKS, 512, SMEM>>>(wt2);
    agg_kernel<false><<<AGG_BLOCKS, 128>>>(b2, g2, be2, bat);

    // layer 3 (+ fused mean-pool accumulation)
    gemm128_kernel<<<GEMM_BLOCKS, 512, SMEM>>>(wt3);
    agg_kernel<true><<<AGG_BLOCKS, 128>>>(b3, g3, be3, bat);

    final_kernel<<<N_GRAPHS, EMB>>>(Wp, bp, out);
}